// round 1
// baseline (speedup 1.0000x reference)
#include <cuda_runtime.h>
#include <cuda_bf16.h>

#define N_NODES 50000
#define N_EDGES 800000
#define N_RELS  65
#define D       64
#define N_GRAPHS 512

#define TILE_M 64
#define MAX_TILES (N_EDGES / TILE_M + N_RELS)   // 12565

// ---------------- scratch (device globals; no allocation) ----------------
__device__ float d_h0[N_NODES * D];
__device__ float d_h1[N_NODES * D];
__device__ float d_agg[N_NODES * D];
__device__ float d_g [N_GRAPHS * D];
__device__ float d_g2[N_GRAPHS * D];

__device__ int d_counts[N_RELS];
__device__ int d_offsets[N_RELS + 1];
__device__ int d_cursor[N_RELS];
__device__ int d_perm[N_EDGES];
__device__ int d_tile_rel [MAX_TILES];
__device__ int d_tile_base[MAX_TILES];
__device__ int d_tile_cnt [MAX_TILES];
__device__ int d_num_tiles;

// ---------------- helpers ----------------
__device__ __forceinline__ void red_add_v4(float* p, float a, float b, float c, float d) {
    asm volatile("red.global.add.v4.f32 [%0], {%1, %2, %3, %4};"
                 :: "l"(p), "f"(a), "f"(b), "f"(c), "f"(d) : "memory");
}

// ---------------- init / zero kernels ----------------
__global__ void init_sort_kernel() {
    int i = threadIdx.x;
    if (i < N_RELS) { d_counts[i] = 0; }
}

__global__ void zero_agg_kernel() {
    int i = blockIdx.x * blockDim.x + threadIdx.x;
    if (i < N_NODES * D) d_agg[i] = 0.0f;
}

__global__ void zero_g_kernel() {
    int i = blockIdx.x * blockDim.x + threadIdx.x;
    if (i < N_GRAPHS * D) d_g[i] = 0.0f;
}

// ---------------- sort by relation ----------------
__global__ void hist_kernel(const int* __restrict__ et) {
    __shared__ int sc[N_RELS];
    for (int i = threadIdx.x; i < N_RELS; i += blockDim.x) sc[i] = 0;
    __syncthreads();
    for (int e = blockIdx.x * blockDim.x + threadIdx.x; e < N_EDGES;
         e += gridDim.x * blockDim.x)
        atomicAdd(&sc[et[e]], 1);
    __syncthreads();
    for (int i = threadIdx.x; i < N_RELS; i += blockDim.x)
        if (sc[i]) atomicAdd(&d_counts[i], sc[i]);
}

__global__ void scan_tiles_kernel() {
    __shared__ int offs[N_RELS];
    __shared__ int tstart[N_RELS];
    if (threadIdx.x == 0) {
        int off = 0, ts = 0;
        for (int r = 0; r < N_RELS; r++) {
            offs[r] = off; tstart[r] = ts;
            d_offsets[r] = off; d_cursor[r] = off;
            int c = d_counts[r];
            off += c;
            ts += (c + TILE_M - 1) / TILE_M;
        }
        d_offsets[N_RELS] = off;
        d_num_tiles = ts;
    }
    __syncthreads();
    for (int r = threadIdx.x; r < N_RELS; r += blockDim.x) {
        int c = d_counts[r];
        int base = offs[r];
        int t0 = tstart[r];
        int nt = (c + TILE_M - 1) / TILE_M;
        for (int t = 0; t < nt; t++) {
            d_tile_rel [t0 + t] = r;
            d_tile_base[t0 + t] = base + t * TILE_M;
            int rem = c - t * TILE_M;
            d_tile_cnt [t0 + t] = rem < TILE_M ? rem : TILE_M;
        }
    }
}

#define SC_EPT 8
__global__ void scatter_kernel(const int* __restrict__ et) {
    __shared__ int lcnt[N_RELS];
    __shared__ int lbase[N_RELS];
    int chunk = blockDim.x * SC_EPT;
    int start = blockIdx.x * chunk;
    for (int i = threadIdx.x; i < N_RELS; i += blockDim.x) lcnt[i] = 0;
    __syncthreads();
    int myrel[SC_EPT];
#pragma unroll
    for (int q = 0; q < SC_EPT; q++) {
        int e = start + threadIdx.x + q * blockDim.x;
        int r = (e < N_EDGES) ? et[e] : -1;
        myrel[q] = r;
        if (r >= 0) atomicAdd(&lcnt[r], 1);
    }
    __syncthreads();
    for (int i = threadIdx.x; i < N_RELS; i += blockDim.x) {
        int c = lcnt[i];
        lbase[i] = c ? atomicAdd(&d_cursor[i], c) : 0;
        lcnt[i] = 0;
    }
    __syncthreads();
#pragma unroll
    for (int q = 0; q < SC_EPT; q++) {
        int e = start + threadIdx.x + q * blockDim.x;
        int r = myrel[q];
        if (r >= 0) {
            int pos = lbase[r] + atomicAdd(&lcnt[r], 1);
            d_perm[pos] = e;
        }
    }
}

// ---------------- RGCN layer: tiled GEMM over relation-sorted edges --------
// One block per tile of 64 edges sharing one relation.
// X[m][d] = h[src[perm[base+m]]][d];  Y = X @ W[rel];  red-add Y rows to agg[dst].
__global__ __launch_bounds__(256) void rgcn_tile_kernel(
    const float* __restrict__ nf, int insel,
    const float* __restrict__ Wall,
    const int* __restrict__ src,
    const int* __restrict__ dst)
{
    __shared__ float Ws[64][68];   // Ws[d][c]
    __shared__ float Xs[64][68];   // Xs[d][m]  (X transposed)
    __shared__ int   s_dst[TILE_M];

    int tile = blockIdx.x;
    if (tile >= d_num_tiles) return;
    int rel  = d_tile_rel[tile];
    int base = d_tile_base[tile];
    int cnt  = d_tile_cnt[tile];
    int tid  = threadIdx.x;

    const float* h = (insel < 0) ? nf : (insel == 0 ? d_h0 : d_h1);

    // load W[rel] (64x64 row-major) into shared
    const float4* Wg = (const float4*)(Wall + (long)rel * 64 * 64);
#pragma unroll
    for (int i = 0; i < 4; i++) {
        int idx = tid + i * 256;        // float4 index 0..1023
        int d  = idx >> 4;
        int c4 = idx & 15;
        float4 v = Wg[idx];
        *(float4*)&Ws[d][c4 * 4] = v;
    }

    // gather X (transposed) + dst: 4 threads per edge, 16 floats each
    {
        int m = tid >> 2;
        int j = tid & 3;
        int e = -1, srow = 0;
        if (m < cnt) { e = d_perm[base + m]; srow = src[e]; }
        if (j == 0) s_dst[m] = (m < cnt) ? dst[e] : -1;
        const float4* hv = (const float4*)(h + (long)srow * 64);
#pragma unroll
        for (int q = 0; q < 4; q++) {
            float4 v = (m < cnt) ? hv[j * 4 + q] : make_float4(0.f, 0.f, 0.f, 0.f);
            int d0 = j * 16 + q * 4;
            Xs[d0 + 0][m] = v.x;
            Xs[d0 + 1][m] = v.y;
            Xs[d0 + 2][m] = v.z;
            Xs[d0 + 3][m] = v.w;
        }
    }
    __syncthreads();

    // compute: each thread -> 4 edges x 4 output cols
    int tx = tid & 15, ty = tid >> 4;
    int m0 = ty * 4, c0 = tx * 4;
    float acc[4][4] = {};
#pragma unroll
    for (int d = 0; d < 64; d++) {
        float4 xv = *(const float4*)&Xs[d][m0];
        float4 wv = *(const float4*)&Ws[d][c0];
        acc[0][0] = fmaf(xv.x, wv.x, acc[0][0]);
        acc[0][1] = fmaf(xv.x, wv.y, acc[0][1]);
        acc[0][2] = fmaf(xv.x, wv.z, acc[0][2]);
        acc[0][3] = fmaf(xv.x, wv.w, acc[0][3]);
        acc[1][0] = fmaf(xv.y, wv.x, acc[1][0]);
        acc[1][1] = fmaf(xv.y, wv.y, acc[1][1]);
        acc[1][2] = fmaf(xv.y, wv.z, acc[1][2]);
        acc[1][3] = fmaf(xv.y, wv.w, acc[1][3]);
        acc[2][0] = fmaf(xv.z, wv.x, acc[2][0]);
        acc[2][1] = fmaf(xv.z, wv.y, acc[2][1]);
        acc[2][2] = fmaf(xv.z, wv.z, acc[2][2]);
        acc[2][3] = fmaf(xv.z, wv.w, acc[2][3]);
        acc[3][0] = fmaf(xv.w, wv.x, acc[3][0]);
        acc[3][1] = fmaf(xv.w, wv.y, acc[3][1]);
        acc[3][2] = fmaf(xv.w, wv.z, acc[3][2]);
        acc[3][3] = fmaf(xv.w, wv.w, acc[3][3]);
    }

    // scatter-add to agg[dst]
#pragma unroll
    for (int i = 0; i < 4; i++) {
        int dn = s_dst[m0 + i];
        if (dn >= 0) {
            float* p = d_agg + (long)dn * 64 + c0;
            red_add_v4(p, acc[i][0], acc[i][1], acc[i][2], acc[i][3]);
        }
    }
}

// ---------------- bias + relu ----------------
__global__ void bias_relu_kernel(const float* __restrict__ b, int outsel) {
    int i = blockIdx.x * blockDim.x + threadIdx.x;
    if (i >= N_NODES * D) return;
    float v = fmaxf(d_agg[i] + b[i & 63], 0.0f);
    if (outsel == 0) d_h0[i] = v; else d_h1[i] = v;
}

// ---------------- graph sum-pool (reads d_h0) ----------------
__global__ void pool_kernel(const int* __restrict__ gid) {
    int idx = blockIdx.x * blockDim.x + threadIdx.x;
    if (idx >= N_NODES * 16) return;
    int n = idx >> 4, c4 = idx & 15;
    float4 v = ((const float4*)(d_h0 + (long)n * 64))[c4];
    float* p = d_g + (long)gid[n] * 64 + c4 * 4;
    red_add_v4(p, v.x, v.y, v.z, v.w);
}

// ---------------- FC layers ----------------
__global__ void fc64_kernel(int insel, int outsel,
                            const float* __restrict__ W,
                            const float* __restrict__ b) {
    int idx = blockIdx.x * blockDim.x + threadIdx.x;
    if (idx >= N_GRAPHS * 64) return;
    int r = idx >> 6, c = idx & 63;
    const float* x = (insel == 0 ? d_g : d_g2) + r * 64;
    float acc = b[c];
#pragma unroll
    for (int d = 0; d < 64; d++) acc = fmaf(x[d], W[d * 64 + c], acc);
    float v = fmaxf(acc, 0.0f);
    if (outsel == 0) d_g[idx] = v; else d_g2[idx] = v;
}

__global__ void pred_kernel(const float* __restrict__ W,
                            const float* __restrict__ b,
                            float* __restrict__ out) {
    int idx = blockIdx.x * blockDim.x + threadIdx.x;
    if (idx >= N_GRAPHS * 2) return;
    int r = idx >> 1, c = idx & 1;
    const float* x = d_g2 + r * 64;
    float acc = b[c];
#pragma unroll
    for (int d = 0; d < 64; d++) acc = fmaf(x[d], W[d * 2 + c], acc);
    out[idx] = acc;
}

// ---------------- launch ----------------
extern "C" void kernel_launch(void* const* d_in, const int* in_sizes, int n_in,
                              void* d_out, int out_size) {
    const float* node_feats = (const float*)d_in[0];
    const int*   etypes     = (const int*)d_in[1];
    const int*   src        = (const int*)d_in[2];
    const int*   dst        = (const int*)d_in[3];
    const int*   gid        = (const int*)d_in[4];
    const float* Wr[3] = { (const float*)d_in[5], (const float*)d_in[7], (const float*)d_in[9] };
    const float* br[3] = { (const float*)d_in[6], (const float*)d_in[8], (const float*)d_in[10] };
    const float* fcW[3] = { (const float*)d_in[11], (const float*)d_in[13], (const float*)d_in[15] };
    const float* fcb[3] = { (const float*)d_in[12], (const float*)d_in[14], (const float*)d_in[16] };
    const float* predW = (const float*)d_in[17];
    const float* predb = (const float*)d_in[18];

    // --- sort edges by relation (recomputed every call; deterministic work) ---
    init_sort_kernel<<<1, 128>>>();
    hist_kernel<<<256, 256>>>(etypes);
    scan_tiles_kernel<<<1, 128>>>();
    scatter_kernel<<<(N_EDGES + 256 * SC_EPT - 1) / (256 * SC_EPT), 256>>>(etypes);

    const int zgrid = (N_NODES * D + 255) / 256;

    // layer selectors: in -1(nf)->out 0 ; in 0 -> out 1 ; in 1 -> out 0
    int insel[3]  = { -1, 0, 1 };
    int outsel[3] = {  0, 1, 0 };
    for (int L = 0; L < 3; L++) {
        zero_agg_kernel<<<zgrid, 256>>>();
        rgcn_tile_kernel<<<MAX_TILES, 256>>>(node_feats, insel[L], Wr[L], src, dst);
        bias_relu_kernel<<<zgrid, 256>>>(br[L], outsel[L]);
    }

    // pool (h lives in d_h0 after layer 3)
    zero_g_kernel<<<(N_GRAPHS * D + 255) / 256, 256>>>();
    pool_kernel<<<(N_NODES * 16 + 255) / 256, 256>>>(gid);

    // FC stack: d_g -> d_g2 -> d_g -> d_g2 -> out
    const int fgrid = (N_GRAPHS * 64 + 255) / 256;
    fc64_kernel<<<fgrid, 256>>>(0, 1, fcW[0], fcb[0]);
    fc64_kernel<<<fgrid, 256>>>(1, 0, fcW[1], fcb[1]);
    fc64_kernel<<<fgrid, 256>>>(0, 1, fcW[2], fcb[2]);
    pred_kernel<<<(N_GRAPHS * 2 + 255) / 256, 256>>>(predW, predb, (float*)d_out);
}

// round 3
// speedup vs baseline: 1.2080x; 1.2080x over previous
#include <cuda_runtime.h>
#include <cuda_bf16.h>
#include <cstdint>

typedef unsigned int uint;

#define N_NODES 50000
#define N_EDGES 800000
#define N_RELS  65
#define D       64
#define N_GRAPHS 512

#define TILE_M 64
#define MAX_TILES (N_EDGES / TILE_M + N_RELS)   // 12565

// ---------------- scratch (device globals; no allocation) ----------------
__device__ float d_h0 [N_NODES * D];
__device__ float d_agg[N_NODES * D];
__device__ float d_g [N_GRAPHS * D];
__device__ float d_g2[N_GRAPHS * D];

__device__ uint d_hhi_u[N_NODES * 32];          // bf16 hi plane, 2 per uint
__device__ uint d_hlo_u[N_NODES * 32];          // bf16 lo plane
__device__ uint d_whi_u[3 * N_RELS * 2048];     // W^T hi: [layer][rel][n=c][k=d]
__device__ uint d_wlo_u[3 * N_RELS * 2048];

__device__ int d_counts[N_RELS];
__device__ int d_cursor[N_RELS];
__device__ int d_perm[N_EDGES];
__device__ int d_tile_rel [MAX_TILES];
__device__ int d_tile_base[MAX_TILES];
__device__ int d_tile_cnt [MAX_TILES];
__device__ int d_num_tiles;

// ---------------- helpers ----------------
__device__ __forceinline__ void red_add_v4(float* p, float a, float b, float c, float d) {
    asm volatile("red.global.add.v4.f32 [%0], {%1, %2, %3, %4};"
                 :: "l"(p), "f"(a), "f"(b), "f"(c), "f"(d) : "memory");
}

__device__ __forceinline__ void mma_bf16(float acc[4], uint a0, uint a1, uint a2, uint a3,
                                         uint b0, uint b1) {
    asm volatile("mma.sync.aligned.m16n8k16.row.col.f32.bf16.bf16.f32 "
                 "{%0,%1,%2,%3}, {%4,%5,%6,%7}, {%8,%9}, {%0,%1,%2,%3};"
                 : "+f"(acc[0]), "+f"(acc[1]), "+f"(acc[2]), "+f"(acc[3])
                 : "r"(a0), "r"(a1), "r"(a2), "r"(a3), "r"(b0), "r"(b1));
}

__device__ __forceinline__ unsigned short bf16_bits(__nv_bfloat16 b) {
    return *reinterpret_cast<unsigned short*>(&b);
}
__device__ __forceinline__ uint packpair(unsigned short a, unsigned short b) {
    return (uint)a | ((uint)b << 16);
}
// split v into bf16 hi + bf16 lo (residual)
__device__ __forceinline__ void split2(float v0, float v1, uint& hi, uint& lo) {
    __nv_bfloat16 h0 = __float2bfloat16_rn(v0);
    __nv_bfloat16 h1 = __float2bfloat16_rn(v1);
    float r0 = v0 - __bfloat162float(h0);
    float r1 = v1 - __bfloat162float(h1);
    __nv_bfloat16 l0 = __float2bfloat16_rn(r0);
    __nv_bfloat16 l1 = __float2bfloat16_rn(r1);
    hi = packpair(bf16_bits(h0), bf16_bits(h1));
    lo = packpair(bf16_bits(l0), bf16_bits(l1));
}

// ---------------- init / zero kernels ----------------
__global__ void init_sort_kernel() {
    int i = threadIdx.x;
    if (i < N_RELS) d_counts[i] = 0;
}
__global__ void zero_agg_kernel() {
    int i = blockIdx.x * blockDim.x + threadIdx.x;
    if (i < N_NODES * D) d_agg[i] = 0.0f;
}
__global__ void zero_g_kernel() {
    int i = blockIdx.x * blockDim.x + threadIdx.x;
    if (i < N_GRAPHS * D) d_g[i] = 0.0f;
}

// ---------------- sort by relation ----------------
__global__ void hist_kernel(const int* __restrict__ et) {
    __shared__ int sc[N_RELS];
    for (int i = threadIdx.x; i < N_RELS; i += blockDim.x) sc[i] = 0;
    __syncthreads();
    for (int e = blockIdx.x * blockDim.x + threadIdx.x; e < N_EDGES; e += gridDim.x * blockDim.x)
        atomicAdd(&sc[et[e]], 1);
    __syncthreads();
    for (int i = threadIdx.x; i < N_RELS; i += blockDim.x)
        if (sc[i]) atomicAdd(&d_counts[i], sc[i]);
}

__global__ void scan_tiles_kernel() {
    __shared__ int offs[N_RELS];
    __shared__ int tstart[N_RELS];
    if (threadIdx.x == 0) {
        int off = 0, ts = 0;
        for (int r = 0; r < N_RELS; r++) {
            offs[r] = off; tstart[r] = ts;
            d_cursor[r] = off;
            int c = d_counts[r];
            off += c;
            ts += (c + TILE_M - 1) / TILE_M;
        }
        d_num_tiles = ts;
    }
    __syncthreads();
    for (int r = threadIdx.x; r < N_RELS; r += blockDim.x) {
        int c = d_counts[r], base = offs[r], t0 = tstart[r];
        int nt = (c + TILE_M - 1) / TILE_M;
        for (int t = 0; t < nt; t++) {
            d_tile_rel [t0 + t] = r;
            d_tile_base[t0 + t] = base + t * TILE_M;
            int rem = c - t * TILE_M;
            d_tile_cnt [t0 + t] = rem < TILE_M ? rem : TILE_M;
        }
    }
}

#define SC_EPT 8
__global__ void scatter_kernel(const int* __restrict__ et) {
    __shared__ int lcnt[N_RELS];
    __shared__ int lbase[N_RELS];
    int start = blockIdx.x * blockDim.x * SC_EPT;
    for (int i = threadIdx.x; i < N_RELS; i += blockDim.x) lcnt[i] = 0;
    __syncthreads();
    int myrel[SC_EPT];
#pragma unroll
    for (int q = 0; q < SC_EPT; q++) {
        int e = start + threadIdx.x + q * blockDim.x;
        int r = (e < N_EDGES) ? et[e] : -1;
        myrel[q] = r;
        if (r >= 0) atomicAdd(&lcnt[r], 1);
    }
    __syncthreads();
    for (int i = threadIdx.x; i < N_RELS; i += blockDim.x) {
        int c = lcnt[i];
        lbase[i] = c ? atomicAdd(&d_cursor[i], c) : 0;
        lcnt[i] = 0;
    }
    __syncthreads();
#pragma unroll
    for (int q = 0; q < SC_EPT; q++) {
        int e = start + threadIdx.x + q * blockDim.x;
        int r = myrel[q];
        if (r >= 0) d_perm[lbase[r] + atomicAdd(&lcnt[r], 1)] = e;
    }
}

// ---------------- precompute: W -> transposed bf16 hi/lo planes ----------------
// one thread per (layer, rel, out-channel c); writes Wt[c][k] contiguous
__global__ void conv_w_kernel(const float* __restrict__ W1,
                              const float* __restrict__ W2,
                              const float* __restrict__ W3) {
    int idx = blockIdx.x * blockDim.x + threadIdx.x;
    if (idx >= 3 * N_RELS * 64) return;
    int l = idx / (N_RELS * 64), rc = idx % (N_RELS * 64);
    int r = rc >> 6, c = rc & 63;
    const float* W = (l == 0 ? W1 : (l == 1 ? W2 : W3)) + (size_t)r * 4096 + c;
    uint4* oh = (uint4*)(d_whi_u + ((size_t)l * N_RELS + r) * 2048);
    uint4* ol = (uint4*)(d_wlo_u + ((size_t)l * N_RELS + r) * 2048);
#pragma unroll
    for (int q = 0; q < 8; q++) {
        uint hu[4], lu[4];
#pragma unroll
        for (int p = 0; p < 4; p++) {
            float v0 = W[(q * 8 + p * 2 + 0) * 64];
            float v1 = W[(q * 8 + p * 2 + 1) * 64];
            split2(v0, v1, hu[p], lu[p]);
        }
        oh[c * 8 + q] = make_uint4(hu[0], hu[1], hu[2], hu[3]);
        ol[c * 8 + q] = make_uint4(lu[0], lu[1], lu[2], lu[3]);
    }
}

// ---------------- precompute: node_feats -> bf16 hi/lo planes ----------------
__global__ void conv_x_kernel(const float* __restrict__ nf) {
    int idx = blockIdx.x * blockDim.x + threadIdx.x;
    if (idx >= N_NODES * 32) return;
    float2 v = ((const float2*)nf)[idx];
    uint hi, lo;
    split2(v.x, v.y, hi, lo);
    d_hhi_u[idx] = hi;
    d_hlo_u[idx] = lo;
}

// ---------------- RGCN layer: mma.sync bf16x3, 64-edge tiles ----------------
// Block = 128 threads (4 warps), one tile of 64 edges sharing one relation.
// A = X (64x64) in SMEM bf16 hi/lo planes; B = W^T (64x64) in SMEM hi/lo.
// Warp w computes rows [16w, 16w+16) x all 64 cols via 4 ksteps x 8 ntiles x 3 terms.
__global__ __launch_bounds__(128) void rgcn_mma_kernel(
    const int* __restrict__ src, const int* __restrict__ dst, int layer)
{
    __shared__ __align__(16) uint sXhi[64 * 36];
    __shared__ __align__(16) uint sXlo[64 * 36];
    __shared__ __align__(16) uint sW  [2 * 64 * 36];   // hi plane, lo plane; reused as fp32 out
    __shared__ int s_dst[TILE_M];

    int tile = blockIdx.x;
    if (tile >= d_num_tiles) return;
    int tid = threadIdx.x;
    int rel  = d_tile_rel[tile];
    int base = d_tile_base[tile];
    int cnt  = d_tile_cnt[tile];

    // ---- stage W^T hi/lo (4096 halves each) into padded SMEM ----
    const uint4* WH = (const uint4*)(d_whi_u + ((size_t)layer * N_RELS + rel) * 2048);
    const uint4* WL = (const uint4*)(d_wlo_u + ((size_t)layer * N_RELS + rel) * 2048);
    uint4* sWhi4 = (uint4*)sW;
    uint4* sWlo4 = (uint4*)(sW + 64 * 36);
#pragma unroll
    for (int i = 0; i < 4; i++) {
        int idx = tid + i * 128;        // 0..511 uint4s per plane
        int n = idx >> 3, c = idx & 7;
        sWhi4[n * 9 + c] = WH[idx];
        sWlo4[n * 9 + c] = WL[idx];
    }

    // ---- gather X rows (2 threads per edge) ----
    {
        int m = tid >> 1, j = tid & 1;
        int e = (m < cnt) ? d_perm[base + m] : -1;
        int srow = (e >= 0) ? src[e] : 0;
        if (j == 0) s_dst[m] = (e >= 0) ? dst[e] : -1;
        const uint4* H  = (const uint4*)d_hhi_u + (size_t)srow * 8;
        const uint4* Lo = (const uint4*)d_hlo_u + (size_t)srow * 8;
        uint4* xh4 = (uint4*)sXhi;
        uint4* xl4 = (uint4*)sXlo;
        uint4 z = make_uint4(0, 0, 0, 0);
#pragma unroll
        for (int q = 0; q < 4; q++) {
            xh4[m * 9 + j * 4 + q] = (m < cnt) ? H [j * 4 + q] : z;
            xl4[m * 9 + j * 4 + q] = (m < cnt) ? Lo[j * 4 + q] : z;
        }
    }
    __syncthreads();

    // ---- compute ----
    int lane = tid & 31, w = tid >> 5;
    int g = lane >> 2, t = lane & 3;
    int r0 = w * 16 + g;

    float acc[8][4];
#pragma unroll
    for (int i = 0; i < 8; i++) { acc[i][0] = acc[i][1] = acc[i][2] = acc[i][3] = 0.f; }

    const uint* WHs = sW;
    const uint* WLs = sW + 64 * 36;
#pragma unroll
    for (int ks = 0; ks < 4; ks++) {
        int ab = r0 * 36 + ks * 8 + t;
        uint ah0 = sXhi[ab],             ah1 = sXhi[ab + 8 * 36];
        uint ah2 = sXhi[ab + 4],         ah3 = sXhi[ab + 8 * 36 + 4];
        uint al0 = sXlo[ab],             al1 = sXlo[ab + 8 * 36];
        uint al2 = sXlo[ab + 4],         al3 = sXlo[ab + 8 * 36 + 4];
#pragma unroll
        for (int nt = 0; nt < 8; nt++) {
            int bb = (nt * 8 + g) * 36 + ks * 8 + t;
            uint bh0 = WHs[bb], bh1 = WHs[bb + 4];
            uint bl0 = WLs[bb], bl1 = WLs[bb + 4];
            mma_bf16(acc[nt], ah0, ah1, ah2, ah3, bh0, bh1);   // hi*hi
            mma_bf16(acc[nt], ah0, ah1, ah2, ah3, bl0, bl1);   // hi*lo
            mma_bf16(acc[nt], al0, al1, al2, al3, bh0, bh1);   // lo*hi
        }
    }

    // ---- stage acc into SMEM (reuse W space), then coalesced v4 red-adds ----
    __syncthreads();                       // all warps done reading W
    float* sOut = (float*)sW;              // 64 rows x 68 floats = 17408B <= 18432B
#pragma unroll
    for (int nt = 0; nt < 8; nt++) {
        int cb = nt * 8 + 2 * t;
        sOut[r0 * 68 + cb]           = acc[nt][0];
        sOut[r0 * 68 + cb + 1]       = acc[nt][1];
        sOut[(r0 + 8) * 68 + cb]     = acc[nt][2];
        sOut[(r0 + 8) * 68 + cb + 1] = acc[nt][3];
    }
    __syncthreads();
    {
        int m = tid >> 1, j = tid & 1;
        int dn = s_dst[m];
        if (dn >= 0) {
            float* p = d_agg + (size_t)dn * 64 + j * 32;
            const float* srw = sOut + m * 68 + j * 32;
#pragma unroll
            for (int q = 0; q < 8; q++) {
                float4 v = *(const float4*)(srw + q * 4);
                red_add_v4(p + q * 4, v.x, v.y, v.z, v.w);
            }
        }
    }
}

// ---------------- bias + relu + bf16 split (writes fp32 h0 + hi/lo planes) ----
__global__ void bias_relu_kernel(const float* __restrict__ b) {
    int idx = blockIdx.x * blockDim.x + threadIdx.x;
    if (idx >= N_NODES * 32) return;
    int c0 = (idx * 2) & 63;
    float2 a = ((const float2*)d_agg)[idx];
    float v0 = fmaxf(a.x + b[c0],     0.0f);
    float v1 = fmaxf(a.y + b[c0 + 1], 0.0f);
    ((float2*)d_h0)[idx] = make_float2(v0, v1);
    uint hi, lo;
    split2(v0, v1, hi, lo);
    d_hhi_u[idx] = hi;
    d_hlo_u[idx] = lo;
}

// ---------------- graph sum-pool (reads d_h0) ----------------
__global__ void pool_kernel(const int* __restrict__ gid) {
    int idx = blockIdx.x * blockDim.x + threadIdx.x;
    if (idx >= N_NODES * 16) return;
    int n = idx >> 4, c4 = idx & 15;
    float4 v = ((const float4*)(d_h0 + (size_t)n * 64))[c4];
    float* p = d_g + (size_t)gid[n] * 64 + c4 * 4;
    red_add_v4(p, v.x, v.y, v.z, v.w);
}

// ---------------- FC layers ----------------
__global__ void fc64_kernel(int insel, int outsel,
                            const float* __restrict__ W,
                            const float* __restrict__ b) {
    int idx = blockIdx.x * blockDim.x + threadIdx.x;
    if (idx >= N_GRAPHS * 64) return;
    int r = idx >> 6, c = idx & 63;
    const float* x = (insel == 0 ? d_g : d_g2) + r * 64;
    float acc = b[c];
#pragma unroll
    for (int d = 0; d < 64; d++) acc = fmaf(x[d], W[d * 64 + c], acc);
    float v = fmaxf(acc, 0.0f);
    if (outsel == 0) d_g[idx] = v; else d_g2[idx] = v;
}

__global__ void pred_kernel(const float* __restrict__ W,
                            const float* __restrict__ b,
                            float* __restrict__ out) {
    int idx = blockIdx.x * blockDim.x + threadIdx.x;
    if (idx >= N_GRAPHS * 2) return;
    int r = idx >> 1, c = idx & 1;
    const float* x = d_g2 + r * 64;
    float acc = b[c];
#pragma unroll
    for (int d = 0; d < 64; d++) acc = fmaf(x[d], W[d * 2 + c], acc);
    out[idx] = acc;
}

// ---------------- launch ----------------
extern "C" void kernel_launch(void* const* d_in, const int* in_sizes, int n_in,
                              void* d_out, int out_size) {
    const float* node_feats = (const float*)d_in[0];
    const int*   etypes     = (const int*)d_in[1];
    const int*   src        = (const int*)d_in[2];
    const int*   dst        = (const int*)d_in[3];
    const int*   gid        = (const int*)d_in[4];
    const float* Wr[3] = { (const float*)d_in[5], (const float*)d_in[7], (const float*)d_in[9] };
    const float* br[3] = { (const float*)d_in[6], (const float*)d_in[8], (const float*)d_in[10] };
    const float* fcW[3] = { (const float*)d_in[11], (const float*)d_in[13], (const float*)d_in[15] };
    const float* fcb[3] = { (const float*)d_in[12], (const float*)d_in[14], (const float*)d_in[16] };
    const float* predW = (const float*)d_in[17];
    const float* predb = (const float*)d_in[18];

    // --- sort edges by relation ---
    init_sort_kernel<<<1, 128>>>();
    hist_kernel<<<256, 256>>>(etypes);
    scan_tiles_kernel<<<1, 128>>>();
    scatter_kernel<<<(N_EDGES + 256 * SC_EPT - 1) / (256 * SC_EPT), 256>>>(etypes);

    // --- precompute bf16 hi/lo planes ---
    conv_w_kernel<<<(3 * N_RELS * 64 + 127) / 128, 128>>>(Wr[0], Wr[1], Wr[2]);
    conv_x_kernel<<<(N_NODES * 32 + 255) / 256, 256>>>(node_feats);

    const int zgrid = (N_NODES * D + 255) / 256;
    const int bgrid = (N_NODES * 32 + 255) / 256;

    for (int L = 0; L < 3; L++) {
        zero_agg_kernel<<<zgrid, 256>>>();
        rgcn_mma_kernel<<<MAX_TILES, 128>>>(src, dst, L);
        bias_relu_kernel<<<bgrid, 256>>>(br[L]);
    }

    zero_g_kernel<<<(N_GRAPHS * D + 255) / 256, 256>>>();
    pool_kernel<<<(N_NODES * 16 + 255) / 256, 256>>>(gid);

    const int fgrid = (N_GRAPHS * 64 + 255) / 256;
    fc64_kernel<<<fgrid, 256>>>(0, 1, fcW[0], fcb[0]);
    fc64_kernel<<<fgrid, 256>>>(1, 0, fcW[1], fcb[1]);
    fc64_kernel<<<fgrid, 256>>>(0, 1, fcW[2], fcb[2]);
    pred_kernel<<<(N_GRAPHS * 2 + 255) / 256, 256>>>(predW, predb, (float*)d_out);
}

// round 4
// speedup vs baseline: 1.2839x; 1.0629x over previous
#include <cuda_runtime.h>
#include <cuda_bf16.h>
#include <cstdint>

typedef unsigned int uint;

#define N_NODES 50000
#define N_EDGES 800000
#define N_RELS  65
#define D       64
#define N_GRAPHS 512

#define TILE_M 128
#define MAX_TILES (N_EDGES / TILE_M + N_RELS)   // 6315

// ---------------- scratch (device globals; no allocation) ----------------
__device__ float d_h0 [N_NODES * D];
__device__ float d_agg[N_NODES * D];
__device__ float d_g [N_GRAPHS * D];
__device__ float d_g2[N_GRAPHS * D];

__device__ uint d_hhi_u[N_NODES * 32];          // bf16 hi plane, 2 per uint
__device__ uint d_hlo_u[N_NODES * 32];          // bf16 lo plane
__device__ uint d_whi_u[3 * N_RELS * 2048];     // W^T hi: [layer][rel][n=c][k=d]
__device__ uint d_wlo_u[3 * N_RELS * 2048];

__device__ int d_counts[N_RELS];
__device__ int d_cursor[N_RELS];
__device__ int d_perm[N_EDGES];
__device__ int d_tile_rel [MAX_TILES];
__device__ int d_tile_base[MAX_TILES];
__device__ int d_tile_cnt [MAX_TILES];
__device__ int d_num_tiles;

// ---------------- helpers ----------------
__device__ __forceinline__ void red_add_v4(float* p, float a, float b, float c, float d) {
    asm volatile("red.global.add.v4.f32 [%0], {%1, %2, %3, %4};"
                 :: "l"(p), "f"(a), "f"(b), "f"(c), "f"(d) : "memory");
}

__device__ __forceinline__ void mma_bf16(float acc[4], const uint a[4], uint b0, uint b1) {
    asm volatile("mma.sync.aligned.m16n8k16.row.col.f32.bf16.bf16.f32 "
                 "{%0,%1,%2,%3}, {%4,%5,%6,%7}, {%8,%9}, {%0,%1,%2,%3};"
                 : "+f"(acc[0]), "+f"(acc[1]), "+f"(acc[2]), "+f"(acc[3])
                 : "r"(a[0]), "r"(a[1]), "r"(a[2]), "r"(a[3]), "r"(b0), "r"(b1));
}

__device__ __forceinline__ void ldsm_x4(uint r[4], uint32_t addr) {
    asm volatile("ldmatrix.sync.aligned.m8n8.x4.shared.b16 {%0,%1,%2,%3}, [%4];"
                 : "=r"(r[0]), "=r"(r[1]), "=r"(r[2]), "=r"(r[3]) : "r"(addr));
}

__device__ __forceinline__ uint32_t smem_u32(const void* p) {
    uint32_t a;
    asm("{ .reg .u64 t; cvta.to.shared.u64 t, %1; cvt.u32.u64 %0, t; }" : "=r"(a) : "l"(p));
    return a;
}

__device__ __forceinline__ unsigned short bf16_bits(__nv_bfloat16 b) {
    return *reinterpret_cast<unsigned short*>(&b);
}
__device__ __forceinline__ uint packpair(unsigned short a, unsigned short b) {
    return (uint)a | ((uint)b << 16);
}
__device__ __forceinline__ void split2(float v0, float v1, uint& hi, uint& lo) {
    __nv_bfloat16 h0 = __float2bfloat16_rn(v0);
    __nv_bfloat16 h1 = __float2bfloat16_rn(v1);
    float r0 = v0 - __bfloat162float(h0);
    float r1 = v1 - __bfloat162float(h1);
    __nv_bfloat16 l0 = __float2bfloat16_rn(r0);
    __nv_bfloat16 l1 = __float2bfloat16_rn(r1);
    hi = packpair(bf16_bits(h0), bf16_bits(h1));
    lo = packpair(bf16_bits(l0), bf16_bits(l1));
}

// ---------------- init / zero kernels ----------------
__global__ void init_sort_kernel() {
    int i = threadIdx.x;
    if (i < N_RELS) d_counts[i] = 0;
}
__global__ void zero_agg_kernel() {
    int i = blockIdx.x * blockDim.x + threadIdx.x;
    if (i < N_NODES * D) d_agg[i] = 0.0f;
}
__global__ void zero_g_kernel() {
    int i = blockIdx.x * blockDim.x + threadIdx.x;
    if (i < N_GRAPHS * D) d_g[i] = 0.0f;
}

// ---------------- sort by relation ----------------
__global__ void hist_kernel(const int* __restrict__ et) {
    __shared__ int sc[N_RELS];
    for (int i = threadIdx.x; i < N_RELS; i += blockDim.x) sc[i] = 0;
    __syncthreads();
    for (int e = blockIdx.x * blockDim.x + threadIdx.x; e < N_EDGES; e += gridDim.x * blockDim.x)
        atomicAdd(&sc[et[e]], 1);
    __syncthreads();
    for (int i = threadIdx.x; i < N_RELS; i += blockDim.x)
        if (sc[i]) atomicAdd(&d_counts[i], sc[i]);
}

__global__ void scan_tiles_kernel() {
    __shared__ int offs[N_RELS];
    __shared__ int tstart[N_RELS];
    if (threadIdx.x == 0) {
        int off = 0, ts = 0;
        for (int r = 0; r < N_RELS; r++) {
            offs[r] = off; tstart[r] = ts;
            d_cursor[r] = off;
            int c = d_counts[r];
            off += c;
            ts += (c + TILE_M - 1) / TILE_M;
        }
        d_num_tiles = ts;
    }
    __syncthreads();
    for (int r = threadIdx.x; r < N_RELS; r += blockDim.x) {
        int c = d_counts[r], base = offs[r], t0 = tstart[r];
        int nt = (c + TILE_M - 1) / TILE_M;
        for (int t = 0; t < nt; t++) {
            d_tile_rel [t0 + t] = r;
            d_tile_base[t0 + t] = base + t * TILE_M;
            int rem = c - t * TILE_M;
            d_tile_cnt [t0 + t] = rem < TILE_M ? rem : TILE_M;
        }
    }
}

#define SC_EPT 8
__global__ void scatter_kernel(const int* __restrict__ et) {
    __shared__ int lcnt[N_RELS];
    __shared__ int lbase[N_RELS];
    int start = blockIdx.x * blockDim.x * SC_EPT;
    for (int i = threadIdx.x; i < N_RELS; i += blockDim.x) lcnt[i] = 0;
    __syncthreads();
    int myrel[SC_EPT];
#pragma unroll
    for (int q = 0; q < SC_EPT; q++) {
        int e = start + threadIdx.x + q * blockDim.x;
        int r = (e < N_EDGES) ? et[e] : -1;
        myrel[q] = r;
        if (r >= 0) atomicAdd(&lcnt[r], 1);
    }
    __syncthreads();
    for (int i = threadIdx.x; i < N_RELS; i += blockDim.x) {
        int c = lcnt[i];
        lbase[i] = c ? atomicAdd(&d_cursor[i], c) : 0;
        lcnt[i] = 0;
    }
    __syncthreads();
#pragma unroll
    for (int q = 0; q < SC_EPT; q++) {
        int e = start + threadIdx.x + q * blockDim.x;
        int r = myrel[q];
        if (r >= 0) d_perm[lbase[r] + atomicAdd(&lcnt[r], 1)] = e;
    }
}

// ---------------- precompute: W -> transposed bf16 hi/lo planes ----------------
__global__ void conv_w_kernel(const float* __restrict__ W1,
                              const float* __restrict__ W2,
                              const float* __restrict__ W3) {
    int idx = blockIdx.x * blockDim.x + threadIdx.x;
    if (idx >= 3 * N_RELS * 64) return;
    int l = idx / (N_RELS * 64), rc = idx % (N_RELS * 64);
    int r = rc >> 6, c = rc & 63;
    const float* W = (l == 0 ? W1 : (l == 1 ? W2 : W3)) + (size_t)r * 4096 + c;
    uint4* oh = (uint4*)(d_whi_u + ((size_t)l * N_RELS + r) * 2048);
    uint4* ol = (uint4*)(d_wlo_u + ((size_t)l * N_RELS + r) * 2048);
#pragma unroll
    for (int q = 0; q < 8; q++) {
        uint hu[4], lu[4];
#pragma unroll
        for (int p = 0; p < 4; p++) {
            float v0 = W[(q * 8 + p * 2 + 0) * 64];
            float v1 = W[(q * 8 + p * 2 + 1) * 64];
            split2(v0, v1, hu[p], lu[p]);
        }
        oh[c * 8 + q] = make_uint4(hu[0], hu[1], hu[2], hu[3]);
        ol[c * 8 + q] = make_uint4(lu[0], lu[1], lu[2], lu[3]);
    }
}

// ---------------- precompute: node_feats -> bf16 hi/lo planes ----------------
__global__ void conv_x_kernel(const float* __restrict__ nf) {
    int idx = blockIdx.x * blockDim.x + threadIdx.x;
    if (idx >= N_NODES * 32) return;
    float2 v = ((const float2*)nf)[idx];
    uint hi, lo;
    split2(v.x, v.y, hi, lo);
    d_hhi_u[idx] = hi;
    d_hlo_u[idx] = lo;
}

// ---------------- RGCN layer: mma.sync bf16x3, 128-edge tiles, ldmatrix ------
// Block = 256 threads (8 warps). X (128x64) + W^T (64x64) bf16 hi/lo in SMEM,
// XOR-swizzled 128B rows (chunk ^= row&7) -> conflict-free ldmatrix.
// Warp w computes rows [16w,16w+16) x 64 cols: 4 ksteps x 4 npairs x 3 terms.
__global__ __launch_bounds__(256) void rgcn_mma_kernel(
    const int* __restrict__ src, const int* __restrict__ dst, int layer)
{
    __shared__ __align__(16) uint smem[12288];   // 48KB exactly
    uint* sXhi = smem;              // 128 rows * 32 uints (128B rows)
    uint* sXlo = smem + 4096;
    uint* sWhi = smem + 8192;       // 64 rows * 32 uints
    uint* sWlo = smem + 10240;

    int tile = blockIdx.x;
    if (tile >= d_num_tiles) return;
    int tid = threadIdx.x;
    int rel  = d_tile_rel[tile];
    int base = d_tile_base[tile];
    int cnt  = d_tile_cnt[tile];

    // ---- stage W^T hi/lo with XOR swizzle ----
    {
        const uint4* WH = (const uint4*)(d_whi_u + ((size_t)layer * N_RELS + rel) * 2048);
        const uint4* WL = (const uint4*)(d_wlo_u + ((size_t)layer * N_RELS + rel) * 2048);
        uint4* wh4 = (uint4*)sWhi;
        uint4* wl4 = (uint4*)sWlo;
#pragma unroll
        for (int i = 0; i < 2; i++) {
            int idx = tid + i * 256;            // 0..511 uint4
            int n = idx >> 3, c = idx & 7;
            int ph = c ^ (n & 7);
            wh4[n * 8 + ph] = WH[idx];
            wl4[n * 8 + ph] = WL[idx];
        }
    }

    // ---- gather X rows (2 threads per edge), dst kept in register ----
    int m = tid >> 1, j = tid & 1;
    int e = (m < cnt) ? d_perm[base + m] : -1;
    int dn = (e >= 0) ? dst[e] : -1;
    int srow = (e >= 0) ? src[e] : 0;
    {
        const uint4* H  = (const uint4*)d_hhi_u + (size_t)srow * 8;
        const uint4* Lo = (const uint4*)d_hlo_u + (size_t)srow * 8;
        uint4* xh4 = (uint4*)sXhi;
        uint4* xl4 = (uint4*)sXlo;
        uint4 z = make_uint4(0, 0, 0, 0);
#pragma unroll
        for (int q = 0; q < 4; q++) {
            int lc = j * 4 + q;
            int ph = lc ^ (m & 7);
            xh4[m * 8 + ph] = (m < cnt) ? H [lc] : z;
            xl4[m * 8 + ph] = (m < cnt) ? Lo[lc] : z;
        }
    }
    __syncthreads();

    // ---- compute ----
    int lane = tid & 31, w = tid >> 5;
    int r0 = w * 16;
    uint xbase = smem_u32(sXhi);
    uint wbase = smem_u32(sWhi);

    int aRow = r0 + (lane & 7) + (lane & 8);
    int aSel = (lane >> 4) & 1;
    int bRowOff = (lane & 7) + ((lane >> 4) & 1) * 8;
    int bSel = (lane >> 3) & 1;

    float acc[8][4];
#pragma unroll
    for (int i = 0; i < 8; i++) { acc[i][0] = acc[i][1] = acc[i][2] = acc[i][3] = 0.f; }

#pragma unroll
    for (int ks = 0; ks < 4; ks++) {
        int aChunk = (ks * 2 + aSel) ^ (aRow & 7);
        uint aAddr = xbase + (uint)(aRow * 128 + aChunk * 16);
        uint ah[4], al[4];
        ldsm_x4(ah, aAddr);
        ldsm_x4(al, aAddr + 16384);            // sXlo = +4096 uints
#pragma unroll
        for (int np = 0; np < 4; np++) {
            int n = np * 16 + bRowOff;
            int bChunk = (ks * 2 + bSel) ^ (n & 7);
            uint bAddr = wbase + (uint)(n * 128 + bChunk * 16);
            uint bh[4], bl[4];
            ldsm_x4(bh, bAddr);
            ldsm_x4(bl, bAddr + 8192);         // sWlo = +2048 uints
            mma_bf16(acc[2 * np],     ah, bh[0], bh[1]);
            mma_bf16(acc[2 * np],     ah, bl[0], bl[1]);
            mma_bf16(acc[2 * np],     al, bh[0], bh[1]);
            mma_bf16(acc[2 * np + 1], ah, bh[2], bh[3]);
            mma_bf16(acc[2 * np + 1], ah, bl[2], bl[3]);
            mma_bf16(acc[2 * np + 1], al, bh[2], bh[3]);
        }
    }

    // ---- stage to SMEM (reuse all of smem), coalesced v4 red-adds ----
    __syncthreads();
    float* sOut = (float*)smem;                // 128 x 68 floats = 34816B
    int g = lane >> 2, t = lane & 3;
#pragma unroll
    for (int nt = 0; nt < 8; nt++) {
        int cb = nt * 8 + 2 * t;
        sOut[(r0 + g) * 68 + cb]         = acc[nt][0];
        sOut[(r0 + g) * 68 + cb + 1]     = acc[nt][1];
        sOut[(r0 + g + 8) * 68 + cb]     = acc[nt][2];
        sOut[(r0 + g + 8) * 68 + cb + 1] = acc[nt][3];
    }
    __syncthreads();
    if (dn >= 0) {
        float* p = d_agg + (size_t)dn * 64 + j * 32;
        const float* srw = sOut + m * 68 + j * 32;
#pragma unroll
        for (int q = 0; q < 8; q++) {
            float4 v = *(const float4*)(srw + q * 4);
            red_add_v4(p + q * 4, v.x, v.y, v.z, v.w);
        }
    }
}

// ---------------- bias + relu + bf16 split ----------------
__global__ void bias_relu_kernel(const float* __restrict__ b) {
    int idx = blockIdx.x * blockDim.x + threadIdx.x;
    if (idx >= N_NODES * 32) return;
    int c0 = (idx * 2) & 63;
    float2 a = ((const float2*)d_agg)[idx];
    float v0 = fmaxf(a.x + b[c0],     0.0f);
    float v1 = fmaxf(a.y + b[c0 + 1], 0.0f);
    ((float2*)d_h0)[idx] = make_float2(v0, v1);
    uint hi, lo;
    split2(v0, v1, hi, lo);
    d_hhi_u[idx] = hi;
    d_hlo_u[idx] = lo;
}

// ---------------- graph sum-pool (reads d_h0) ----------------
__global__ void pool_kernel(const int* __restrict__ gid) {
    int idx = blockIdx.x * blockDim.x + threadIdx.x;
    if (idx >= N_NODES * 16) return;
    int n = idx >> 4, c4 = idx & 15;
    float4 v = ((const float4*)(d_h0 + (size_t)n * 64))[c4];
    float* p = d_g + (size_t)gid[n] * 64 + c4 * 4;
    red_add_v4(p, v.x, v.y, v.z, v.w);
}

// ---------------- FC layers ----------------
__global__ void fc64_kernel(int insel, int outsel,
                            const float* __restrict__ W,
                            const float* __restrict__ b) {
    int idx = blockIdx.x * blockDim.x + threadIdx.x;
    if (idx >= N_GRAPHS * 64) return;
    int r = idx >> 6, c = idx & 63;
    const float* x = (insel == 0 ? d_g : d_g2) + r * 64;
    float acc = b[c];
#pragma unroll
    for (int d = 0; d < 64; d++) acc = fmaf(x[d], W[d * 64 + c], acc);
    float v = fmaxf(acc, 0.0f);
    if (outsel == 0) d_g[idx] = v; else d_g2[idx] = v;
}

__global__ void pred_kernel(const float* __restrict__ W,
                            const float* __restrict__ b,
                            float* __restrict__ out) {
    int idx = blockIdx.x * blockDim.x + threadIdx.x;
    if (idx >= N_GRAPHS * 2) return;
    int r = idx >> 1, c = idx & 1;
    const float* x = d_g2 + r * 64;
    float acc = b[c];
#pragma unroll
    for (int d = 0; d < 64; d++) acc = fmaf(x[d], W[d * 2 + c], acc);
    out[idx] = acc;
}

// ---------------- launch ----------------
extern "C" void kernel_launch(void* const* d_in, const int* in_sizes, int n_in,
                              void* d_out, int out_size) {
    const float* node_feats = (const float*)d_in[0];
    const int*   etypes     = (const int*)d_in[1];
    const int*   src        = (const int*)d_in[2];
    const int*   dst        = (const int*)d_in[3];
    const int*   gid        = (const int*)d_in[4];
    const float* Wr[3] = { (const float*)d_in[5], (const float*)d_in[7], (const float*)d_in[9] };
    const float* br[3] = { (const float*)d_in[6], (const float*)d_in[8], (const float*)d_in[10] };
    const float* fcW[3] = { (const float*)d_in[11], (const float*)d_in[13], (const float*)d_in[15] };
    const float* fcb[3] = { (const float*)d_in[12], (const float*)d_in[14], (const float*)d_in[16] };
    const float* predW = (const float*)d_in[17];
    const float* predb = (const float*)d_in[18];

    // --- sort edges by relation ---
    init_sort_kernel<<<1, 128>>>();
    hist_kernel<<<256, 256>>>(etypes);
    scan_tiles_kernel<<<1, 128>>>();
    scatter_kernel<<<(N_EDGES + 256 * SC_EPT - 1) / (256 * SC_EPT), 256>>>(etypes);

    // --- precompute bf16 hi/lo planes ---
    conv_w_kernel<<<(3 * N_RELS * 64 + 127) / 128, 128>>>(Wr[0], Wr[1], Wr[2]);
    conv_x_kernel<<<(N_NODES * 32 + 255) / 256, 256>>>(node_feats);

    const int zgrid = (N_NODES * D + 255) / 256;
    const int bgrid = (N_NODES * 32 + 255) / 256;

    for (int L = 0; L < 3; L++) {
        zero_agg_kernel<<<zgrid, 256>>>();
        rgcn_mma_kernel<<<MAX_TILES, 256>>>(src, dst, L);
        bias_relu_kernel<<<bgrid, 256>>>(br[L]);
    }

    zero_g_kernel<<<(N_GRAPHS * D + 255) / 256, 256>>>();
    pool_kernel<<<(N_NODES * 16 + 255) / 256, 256>>>(gid);

    const int fgrid = (N_GRAPHS * 64 + 255) / 256;
    fc64_kernel<<<fgrid, 256>>>(0, 1, fcW[0], fcb[0]);
    fc64_kernel<<<fgrid, 256>>>(1, 0, fcW[1], fcb[1]);
    fc64_kernel<<<fgrid, 256>>>(0, 1, fcW[2], fcb[2]);
    pred_kernel<<<(N_GRAPHS * 2 + 255) / 256, 256>>>(predW, predb, (float*)d_out);
}

// round 5
// speedup vs baseline: 1.3323x; 1.0376x over previous
#include <cuda_runtime.h>
#include <cuda_bf16.h>
#include <cstdint>

typedef unsigned int uint;

#define N_NODES 50000
#define N_EDGES 800000
#define N_RELS  65
#define D       64
#define N_GRAPHS 512

#define TILE_M 128
#define MAX_TILES (N_EDGES / TILE_M + N_RELS)   // 6315
#define P_BLOCKS 296
#define RGCN_SMEM 81920   // 2x32KB X bufs + 16KB W

// ---------------- scratch (device globals; no allocation) ----------------
__device__ float d_h0 [N_NODES * D];
__device__ float d_agg[N_NODES * D];
__device__ float d_g [N_GRAPHS * D];
__device__ float d_g2[N_GRAPHS * D];

__device__ uint d_hhi_u[N_NODES * 32];          // bf16 hi plane, 2 per uint
__device__ uint d_hlo_u[N_NODES * 32];          // bf16 lo plane
__device__ uint d_whi_u[3 * N_RELS * 2048];     // W^T hi: [layer][rel][n=c][k=d]
__device__ uint d_wlo_u[3 * N_RELS * 2048];

__device__ int d_counts[N_RELS];
__device__ int d_cursor[N_RELS];
__device__ int d_psrc[N_EDGES];                 // src[perm[i]]
__device__ int d_pdst[N_EDGES];                 // dst[perm[i]]
__device__ int d_tile_rel [MAX_TILES];
__device__ int d_tile_base[MAX_TILES];
__device__ int d_tile_cnt [MAX_TILES];
__device__ int d_num_tiles;

// ---------------- helpers ----------------
__device__ __forceinline__ void red_add_v4(float* p, float a, float b, float c, float d) {
    asm volatile("red.global.add.v4.f32 [%0], {%1, %2, %3, %4};"
                 :: "l"(p), "f"(a), "f"(b), "f"(c), "f"(d) : "memory");
}

__device__ __forceinline__ void mma_bf16(float acc[4], const uint a[4], uint b0, uint b1) {
    asm volatile("mma.sync.aligned.m16n8k16.row.col.f32.bf16.bf16.f32 "
                 "{%0,%1,%2,%3}, {%4,%5,%6,%7}, {%8,%9}, {%0,%1,%2,%3};"
                 : "+f"(acc[0]), "+f"(acc[1]), "+f"(acc[2]), "+f"(acc[3])
                 : "r"(a[0]), "r"(a[1]), "r"(a[2]), "r"(a[3]), "r"(b0), "r"(b1));
}

__device__ __forceinline__ void ldsm_x4(uint r[4], uint32_t addr) {
    asm volatile("ldmatrix.sync.aligned.m8n8.x4.shared.b16 {%0,%1,%2,%3}, [%4];"
                 : "=r"(r[0]), "=r"(r[1]), "=r"(r[2]), "=r"(r[3]) : "r"(addr));
}

__device__ __forceinline__ uint32_t smem_u32(const void* p) {
    uint32_t a;
    asm("{ .reg .u64 t; cvta.to.shared.u64 t, %1; cvt.u32.u64 %0, t; }" : "=r"(a) : "l"(p));
    return a;
}

__device__ __forceinline__ unsigned short bf16_bits(__nv_bfloat16 b) {
    return *reinterpret_cast<unsigned short*>(&b);
}
__device__ __forceinline__ uint packpair(unsigned short a, unsigned short b) {
    return (uint)a | ((uint)b << 16);
}
__device__ __forceinline__ void split2(float v0, float v1, uint& hi, uint& lo) {
    __nv_bfloat16 h0 = __float2bfloat16_rn(v0);
    __nv_bfloat16 h1 = __float2bfloat16_rn(v1);
    float r0 = v0 - __bfloat162float(h0);
    float r1 = v1 - __bfloat162float(h1);
    __nv_bfloat16 l0 = __float2bfloat16_rn(r0);
    __nv_bfloat16 l1 = __float2bfloat16_rn(r1);
    hi = packpair(bf16_bits(h0), bf16_bits(h1));
    lo = packpair(bf16_bits(l0), bf16_bits(l1));
}

// ---------------- init / zero kernels ----------------
__global__ void init_sort_kernel() {
    int i = threadIdx.x;
    if (i < N_RELS) d_counts[i] = 0;
}
__global__ void zero_agg_kernel() {
    int i = blockIdx.x * blockDim.x + threadIdx.x;
    if (i < N_NODES * D) d_agg[i] = 0.0f;
}
__global__ void zero_g_kernel() {
    int i = blockIdx.x * blockDim.x + threadIdx.x;
    if (i < N_GRAPHS * D) d_g[i] = 0.0f;
}

// ---------------- sort by relation ----------------
__global__ void hist_kernel(const int* __restrict__ et) {
    __shared__ int sc[N_RELS];
    for (int i = threadIdx.x; i < N_RELS; i += blockDim.x) sc[i] = 0;
    __syncthreads();
    for (int e = blockIdx.x * blockDim.x + threadIdx.x; e < N_EDGES; e += gridDim.x * blockDim.x)
        atomicAdd(&sc[et[e]], 1);
    __syncthreads();
    for (int i = threadIdx.x; i < N_RELS; i += blockDim.x)
        if (sc[i]) atomicAdd(&d_counts[i], sc[i]);
}

__global__ void scan_tiles_kernel() {
    __shared__ int offs[N_RELS];
    __shared__ int tstart[N_RELS];
    if (threadIdx.x == 0) {
        int off = 0, ts = 0;
        for (int r = 0; r < N_RELS; r++) {
            offs[r] = off; tstart[r] = ts;
            d_cursor[r] = off;
            int c = d_counts[r];
            off += c;
            ts += (c + TILE_M - 1) / TILE_M;
        }
        d_num_tiles = ts;
    }
    __syncthreads();
    for (int r = threadIdx.x; r < N_RELS; r += blockDim.x) {
        int c = d_counts[r], base = offs[r], t0 = tstart[r];
        int nt = (c + TILE_M - 1) / TILE_M;
        for (int t = 0; t < nt; t++) {
            d_tile_rel [t0 + t] = r;
            d_tile_base[t0 + t] = base + t * TILE_M;
            int rem = c - t * TILE_M;
            d_tile_cnt [t0 + t] = rem < TILE_M ? rem : TILE_M;
        }
    }
}

#define SC_EPT 8
__global__ void scatter_kernel(const int* __restrict__ et,
                               const int* __restrict__ src,
                               const int* __restrict__ dst) {
    __shared__ int lcnt[N_RELS];
    __shared__ int lbase[N_RELS];
    int start = blockIdx.x * blockDim.x * SC_EPT;
    for (int i = threadIdx.x; i < N_RELS; i += blockDim.x) lcnt[i] = 0;
    __syncthreads();
    int myrel[SC_EPT];
#pragma unroll
    for (int q = 0; q < SC_EPT; q++) {
        int e = start + threadIdx.x + q * blockDim.x;
        int r = (e < N_EDGES) ? et[e] : -1;
        myrel[q] = r;
        if (r >= 0) atomicAdd(&lcnt[r], 1);
    }
    __syncthreads();
    for (int i = threadIdx.x; i < N_RELS; i += blockDim.x) {
        int c = lcnt[i];
        lbase[i] = c ? atomicAdd(&d_cursor[i], c) : 0;
        lcnt[i] = 0;
    }
    __syncthreads();
#pragma unroll
    for (int q = 0; q < SC_EPT; q++) {
        int e = start + threadIdx.x + q * blockDim.x;
        int r = myrel[q];
        if (r >= 0) {
            int pos = lbase[r] + atomicAdd(&lcnt[r], 1);
            d_psrc[pos] = src[e];
            d_pdst[pos] = dst[e];
        }
    }
}

// ---------------- precompute: W -> transposed bf16 hi/lo planes ----------------
__global__ void conv_w_kernel(const float* __restrict__ W1,
                              const float* __restrict__ W2,
                              const float* __restrict__ W3) {
    int idx = blockIdx.x * blockDim.x + threadIdx.x;
    if (idx >= 3 * N_RELS * 64) return;
    int l = idx / (N_RELS * 64), rc = idx % (N_RELS * 64);
    int r = rc >> 6, c = rc & 63;
    const float* W = (l == 0 ? W1 : (l == 1 ? W2 : W3)) + (size_t)r * 4096 + c;
    uint4* oh = (uint4*)(d_whi_u + ((size_t)l * N_RELS + r) * 2048);
    uint4* ol = (uint4*)(d_wlo_u + ((size_t)l * N_RELS + r) * 2048);
#pragma unroll
    for (int q = 0; q < 8; q++) {
        uint hu[4], lu[4];
#pragma unroll
        for (int p = 0; p < 4; p++) {
            float v0 = W[(q * 8 + p * 2 + 0) * 64];
            float v1 = W[(q * 8 + p * 2 + 1) * 64];
            split2(v0, v1, hu[p], lu[p]);
        }
        oh[c * 8 + q] = make_uint4(hu[0], hu[1], hu[2], hu[3]);
        ol[c * 8 + q] = make_uint4(lu[0], lu[1], lu[2], lu[3]);
    }
}

// ---------------- precompute: node_feats -> bf16 hi/lo planes ----------------
__global__ void conv_x_kernel(const float* __restrict__ nf) {
    int idx = blockIdx.x * blockDim.x + threadIdx.x;
    if (idx >= N_NODES * 32) return;
    float2 v = ((const float2*)nf)[idx];
    uint hi, lo;
    split2(v.x, v.y, hi, lo);
    d_hhi_u[idx] = hi;
    d_hlo_u[idx] = lo;
}

// ---------------- RGCN layer: pipelined persistent-chunk mma kernel ----------
// SMEM bytes: buf0 Xhi [0,16K) Xlo [16K,32K); buf1 Xhi [32K,48K) Xlo [48K,64K);
//             Whi [64K,72K) Wlo [72K,80K).
// Output staging reuses the just-consumed X buffer (XOR-swizzled, 256B rows).
__global__ __launch_bounds__(256) void rgcn_mma_kernel(int layer)
{
    extern __shared__ __align__(16) uint smem[];
    int nt_total = d_num_tiles;
    int k = (nt_total + P_BLOCKS - 1) / P_BLOCKS;
    int t0 = (int)blockIdx.x * k;
    int t1 = t0 + k; if (t1 > nt_total) t1 = nt_total;
    if (t0 >= t1) return;

    int tid = threadIdx.x;
    int m = tid >> 1, j = tid & 1;
    uint sbase = smem_u32(smem);

    int lane = tid & 31, w = tid >> 5;
    int r0 = w * 16;
    int aRow = r0 + (lane & 7) + (lane & 8);
    int aSel = (lane >> 4) & 1;
    int bRowOff = (lane & 7) + ((lane >> 4) & 1) * 8;
    int bSel = (lane >> 3) & 1;
    int g = lane >> 2, tq = lane & 3;

    int cur_rel = -1;
    int dn_next = -1;

    auto prefetch = [&](int t, int buf) {
        int base = d_tile_base[t];
        int cnt  = d_tile_cnt[t];
        int ei = base + m;
        int eic = ei < (N_EDGES - 1) ? ei : (N_EDGES - 1);
        int srow = d_psrc[eic];
        dn_next = (m < cnt) ? d_pdst[eic] : -1;
        uint ssz = (m < cnt) ? 16u : 0u;
        const char* ghi = (const char*)(d_hhi_u + (size_t)srow * 32);
        const char* glo = (const char*)(d_hlo_u + (size_t)srow * 32);
        uint xb = sbase + (uint)buf * 32768u + (uint)m * 128u;
#pragma unroll
        for (int q = 0; q < 4; q++) {
            int lc = j * 4 + q;
            int ph = lc ^ (m & 7);
            asm volatile("cp.async.ca.shared.global [%0], [%1], 16, %2;"
                         :: "r"(xb + (uint)ph * 16u), "l"(ghi + lc * 16), "r"(ssz) : "memory");
            asm volatile("cp.async.ca.shared.global [%0], [%1], 16, %2;"
                         :: "r"(xb + 16384u + (uint)ph * 16u), "l"(glo + lc * 16), "r"(ssz) : "memory");
        }
        asm volatile("cp.async.commit_group;" ::: "memory");
    };

    prefetch(t0, 0);

    for (int t = t0; t < t1; t++) {
        int buf = (t - t0) & 1;
        int dn_cur = dn_next;

        if (t > t0) __syncthreads();                  // staging reads of t-1 done
        bool has_next = (t + 1 < t1);
        if (has_next) prefetch(t + 1, buf ^ 1);

        int rel = d_tile_rel[t];
        if (rel != cur_rel) {
            cur_rel = rel;
            const uint4* WH = (const uint4*)(d_whi_u + ((size_t)layer * N_RELS + rel) * 2048);
            const uint4* WL = (const uint4*)(d_wlo_u + ((size_t)layer * N_RELS + rel) * 2048);
            uint4* wh4 = (uint4*)((char*)smem + 65536);
            uint4* wl4 = (uint4*)((char*)smem + 65536 + 8192);
#pragma unroll
            for (int i = 0; i < 2; i++) {
                int idx = tid + i * 256;
                int n = idx >> 3, c = idx & 7;
                int ph = c ^ (n & 7);
                wh4[n * 8 + ph] = WH[idx];
                wl4[n * 8 + ph] = WL[idx];
            }
        }

        if (has_next) asm volatile("cp.async.wait_group 1;" ::: "memory");
        else          asm volatile("cp.async.wait_group 0;" ::: "memory");
        __syncthreads();                              // X[t] + W visible

        uint xbB = sbase + (uint)buf * 32768u;
        uint wbB = sbase + 65536u;

        float acc[8][4];
#pragma unroll
        for (int i = 0; i < 8; i++) { acc[i][0] = acc[i][1] = acc[i][2] = acc[i][3] = 0.f; }

#pragma unroll
        for (int ks = 0; ks < 4; ks++) {
            int aChunk = (ks * 2 + aSel) ^ (aRow & 7);
            uint aAddr = xbB + (uint)(aRow * 128 + aChunk * 16);
            uint ah[4], al[4];
            ldsm_x4(ah, aAddr);
            ldsm_x4(al, aAddr + 16384u);
#pragma unroll
            for (int np = 0; np < 4; np++) {
                int n = np * 16 + bRowOff;
                int bChunk = (ks * 2 + bSel) ^ (n & 7);
                uint bAddr = wbB + (uint)(n * 128 + bChunk * 16);
                uint bh[4], bl[4];
                ldsm_x4(bh, bAddr);
                ldsm_x4(bl, bAddr + 8192u);
                mma_bf16(acc[2 * np],     ah, bh[0], bh[1]);
                mma_bf16(acc[2 * np],     ah, bl[0], bl[1]);
                mma_bf16(acc[2 * np],     al, bh[0], bh[1]);
                mma_bf16(acc[2 * np + 1], ah, bh[2], bh[3]);
                mma_bf16(acc[2 * np + 1], ah, bl[2], bl[3]);
                mma_bf16(acc[2 * np + 1], al, bh[2], bh[3]);
            }
        }
        __syncthreads();                              // ldsm reads of buf done

        // stage into the dead X buffer (XOR layout, 64-float rows)
        float* sOutF = (float*)((char*)smem + (size_t)buf * 32768);
#pragma unroll
        for (int nt = 0; nt < 8; nt++) {
            int cb = nt * 8 + 2 * tq;
            int pc = cb ^ (g << 3);
            *(float2*)&sOutF[(r0 + g) * 64 + pc]     = make_float2(acc[nt][0], acc[nt][1]);
            *(float2*)&sOutF[(r0 + g + 8) * 64 + pc] = make_float2(acc[nt][2], acc[nt][3]);
        }
        __syncthreads();                              // staging visible

        if (dn_cur >= 0) {
            float* p = d_agg + (size_t)dn_cur * 64;
            const float* srw = sOutF + m * 64;
#pragma unroll
            for (int q = 0; q < 8; q++) {
                int c4 = j * 32 + q * 4;
                int pc = c4 ^ ((m & 7) << 3);
                float4 v = *(const float4*)(srw + pc);
                red_add_v4(p + c4, v.x, v.y, v.z, v.w);
            }
        }
    }
}

// ---------------- bias + relu + bf16 split ----------------
__global__ void bias_relu_kernel(const float* __restrict__ b) {
    int idx = blockIdx.x * blockDim.x + threadIdx.x;
    if (idx >= N_NODES * 32) return;
    int c0 = (idx * 2) & 63;
    float2 a = ((const float2*)d_agg)[idx];
    float v0 = fmaxf(a.x + b[c0],     0.0f);
    float v1 = fmaxf(a.y + b[c0 + 1], 0.0f);
    ((float2*)d_h0)[idx] = make_float2(v0, v1);
    uint hi, lo;
    split2(v0, v1, hi, lo);
    d_hhi_u[idx] = hi;
    d_hlo_u[idx] = lo;
}

// ---------------- graph sum-pool (reads d_h0) ----------------
__global__ void pool_kernel(const int* __restrict__ gid) {
    int idx = blockIdx.x * blockDim.x + threadIdx.x;
    if (idx >= N_NODES * 16) return;
    int n = idx >> 4, c4 = idx & 15;
    float4 v = ((const float4*)(d_h0 + (size_t)n * 64))[c4];
    float* p = d_g + (size_t)gid[n] * 64 + c4 * 4;
    red_add_v4(p, v.x, v.y, v.z, v.w);
}

// ---------------- FC layers ----------------
__global__ void fc64_kernel(int insel, int outsel,
                            const float* __restrict__ W,
                            const float* __restrict__ b) {
    int idx = blockIdx.x * blockDim.x + threadIdx.x;
    if (idx >= N_GRAPHS * 64) return;
    int r = idx >> 6, c = idx & 63;
    const float* x = (insel == 0 ? d_g : d_g2) + r * 64;
    float acc = b[c];
#pragma unroll
    for (int d = 0; d < 64; d++) acc = fmaf(x[d], W[d * 64 + c], acc);
    float v = fmaxf(acc, 0.0f);
    if (outsel == 0) d_g[idx] = v; else d_g2[idx] = v;
}

__global__ void pred_kernel(const float* __restrict__ W,
                            const float* __restrict__ b,
                            float* __restrict__ out) {
    int idx = blockIdx.x * blockDim.x + threadIdx.x;
    if (idx >= N_GRAPHS * 2) return;
    int r = idx >> 1, c = idx & 1;
    const float* x = d_g2 + r * 64;
    float acc = b[c];
#pragma unroll
    for (int d = 0; d < 64; d++) acc = fmaf(x[d], W[d * 2 + c], acc);
    out[idx] = acc;
}

// ---------------- launch ----------------
extern "C" void kernel_launch(void* const* d_in, const int* in_sizes, int n_in,
                              void* d_out, int out_size) {
    const float* node_feats = (const float*)d_in[0];
    const int*   etypes     = (const int*)d_in[1];
    const int*   src        = (const int*)d_in[2];
    const int*   dst        = (const int*)d_in[3];
    const int*   gid        = (const int*)d_in[4];
    const float* Wr[3] = { (const float*)d_in[5], (const float*)d_in[7], (const float*)d_in[9] };
    const float* br[3] = { (const float*)d_in[6], (const float*)d_in[8], (const float*)d_in[10] };
    const float* fcW[3] = { (const float*)d_in[11], (const float*)d_in[13], (const float*)d_in[15] };
    const float* fcb[3] = { (const float*)d_in[12], (const float*)d_in[14], (const float*)d_in[16] };
    const float* predW = (const float*)d_in[17];
    const float* predb = (const float*)d_in[18];

    static int smem_set = 0;
    if (!smem_set) {
        cudaFuncSetAttribute(rgcn_mma_kernel,
                             cudaFuncAttributeMaxDynamicSharedMemorySize, RGCN_SMEM);
        smem_set = 1;
    }

    // --- sort edges by relation (psrc/pdst precomputed in sorted order) ---
    init_sort_kernel<<<1, 128>>>();
    hist_kernel<<<256, 256>>>(etypes);
    scan_tiles_kernel<<<1, 128>>>();
    scatter_kernel<<<(N_EDGES + 256 * SC_EPT - 1) / (256 * SC_EPT), 256>>>(etypes, src, dst);

    // --- precompute bf16 hi/lo planes ---
    conv_w_kernel<<<(3 * N_RELS * 64 + 127) / 128, 128>>>(Wr[0], Wr[1], Wr[2]);
    conv_x_kernel<<<(N_NODES * 32 + 255) / 256, 256>>>(node_feats);

    const int zgrid = (N_NODES * D + 255) / 256;
    const int bgrid = (N_NODES * 32 + 255) / 256;

    for (int L = 0; L < 3; L++) {
        zero_agg_kernel<<<zgrid, 256>>>();
        rgcn_mma_kernel<<<P_BLOCKS, 256, RGCN_SMEM>>>(L);
        bias_relu_kernel<<<bgrid, 256>>>(br[L]);
    }

    zero_g_kernel<<<(N_GRAPHS * D + 255) / 256, 256>>>();
    pool_kernel<<<(N_NODES * 16 + 255) / 256, 256>>>(gid);

    const int fgrid = (N_GRAPHS * 64 + 255) / 256;
    fc64_kernel<<<fgrid, 256>>>(0, 1, fcW[0], fcb[0]);
    fc64_kernel<<<fgrid, 256>>>(1, 0, fcW[1], fcb[1]);
    fc64_kernel<<<fgrid, 256>>>(0, 1, fcW[2], fcb[2]);
    pred_kernel<<<(N_GRAPHS * 2 + 255) / 256, 256>>>(predW, predb, (float*)d_out);
}